// round 3
// baseline (speedup 1.0000x reference)
#include <cuda_runtime.h>
#include <cuda_bf16.h>

// Problem constants: B=512, S=32768, alpha=0.1, beta=0.9
#define B_CONST 512
#define S_CONST 32768

// log(0.1), log(0.9). Note log(1-alpha)=log(beta), log(1-beta)=log(alpha).
#define LOG_A   (-2.3025850929940457f)   // log(0.1)
#define LOG_1A  (-0.10536051565782628f)  // log(0.9)
#define LOG_B   (-0.10536051565782628f)  // log(0.9)
#define LOG_1B  (-2.3025850929940457f)   // log(0.1)

constexpr int THREADS = 256;
constexpr int IT      = 16;                 // s-values per thread
constexpr int CHUNK   = THREADS * IT;       // 4096 s per block
constexpr int BPR     = S_CONST / CHUNK;    // 8 blocks per row
constexpr int GRID    = B_CONST * BPR;      // 4096 blocks

__device__ float        g_partials[GRID];
__device__ unsigned int g_count;            // zero-init; last block resets

// KL transition term: prev=(pp0,pp1), curr=(q0,q1)
__device__ __forceinline__ float div_term(float pp0, float pp1,
                                          float q0, float q1)
{
    float l0 = __logf(q0);
    float l1 = __logf(q1);
    float t1 = q1 * (l1 - LOG_B)  + q0 * (l0 - LOG_1B);
    float t2 = q1 * (l1 - LOG_1B) + q0 * (l0 - LOG_B);
    return pp1 * t1 + pp0 * t2;
}

__global__ __launch_bounds__(THREADS)
void ekl_fused_kernel(const float* __restrict__ post,
                      const int* __restrict__ length,
                      float* __restrict__ out)
{
    const int bid = blockIdx.x;
    const int b   = bid / BPR;
    const int c   = bid % BPR;
    const int len = length[b];        // 1 <= len <= S
    const int s0  = c * CHUNK;

    float sum = 0.0f;

    if (s0 < len) {
        const float2* row = reinterpret_cast<const float2*>(post)
                            + (size_t)b * S_CONST;
        const int sbase = s0 + threadIdx.x * IT;

        if (sbase < len) {
            // 8 consecutive float4 loads (128B per thread, 16B-aligned).
            float c0[IT], c1[IT];
            const float4* v = reinterpret_cast<const float4*>(row + sbase);
            #pragma unroll
            for (int i = 0; i < IT / 2; ++i) {
                float4 q = v[i];
                c0[2*i]   = q.x; c1[2*i]   = q.y;
                c0[2*i+1] = q.z; c1[2*i+1] = q.w;
            }

            if (sbase > 0 && sbase + IT <= len) {
                // Fast path: all IT transitions valid, no per-element checks.
                float2 pv = row[sbase - 1];
                float pp0 = pv.x, pp1 = pv.y;
                #pragma unroll
                for (int i = 0; i < IT; ++i) {
                    sum += div_term(pp0, pp1, c0[i], c1[i]);
                    pp0 = c0[i]; pp1 = c1[i];
                }
            } else {
                // Slow path: chunk head (s==0 first term) or masked tail.
                float pp0, pp1;
                if (sbase > 0) {
                    float2 pv = row[sbase - 1];
                    pp0 = pv.x; pp1 = pv.y;
                } else {
                    float l0 = __logf(c0[0]);
                    float l1 = __logf(c1[0]);
                    sum += c1[0] * (l1 - LOG_A) + c0[0] * (l0 - LOG_1A);
                    pp0 = 0.0f; pp1 = 0.0f;   // unused (s>=1 guard)
                }
                #pragma unroll
                for (int i = 0; i < IT; ++i) {
                    const int s = sbase + i;
                    if (s >= 1 && s < len)
                        sum += div_term(pp0, pp1, c0[i], c1[i]);
                    pp0 = c0[i]; pp1 = c1[i];
                }
            }
        }
    }

    // Deterministic block reduction: warp shuffle tree + smem
    #pragma unroll
    for (int off = 16; off > 0; off >>= 1)
        sum += __shfl_down_sync(0xffffffffu, sum, off);

    __shared__ float wsum[THREADS / 32];
    const int lane = threadIdx.x & 31;
    const int wid  = threadIdx.x >> 5;
    if (lane == 0) wsum[wid] = sum;
    __syncthreads();

    if (wid == 0) {
        float v = (lane < THREADS / 32) ? wsum[lane] : 0.0f;
        #pragma unroll
        for (int off = 4; off > 0; off >>= 1)
            v += __shfl_down_sync(0xffffffffu, v, off);
        if (lane == 0) g_partials[bid] = v;
    }

    // Last-block-wins final reduction (single launch, graph-replayable).
    __shared__ bool is_last;
    if (threadIdx.x == 0) {
        __threadfence();
        unsigned int t = atomicAdd(&g_count, 1u);
        is_last = (t == GRID - 1);
    }
    __syncthreads();

    if (is_last) {
        __threadfence();
        // Fixed per-thread strided order -> deterministic.
        float s = 0.0f;
        #pragma unroll
        for (int i = 0; i < GRID / THREADS; ++i)
            s += g_partials[threadIdx.x + i * THREADS];

        #pragma unroll
        for (int off = 16; off > 0; off >>= 1)
            s += __shfl_down_sync(0xffffffffu, s, off);

        if (lane == 0) wsum[wid] = s;
        __syncthreads();

        if (wid == 0) {
            float v = (lane < THREADS / 32) ? wsum[lane] : 0.0f;
            #pragma unroll
            for (int off = 4; off > 0; off >>= 1)
                v += __shfl_down_sync(0xffffffffu, v, off);
            if (lane == 0) {
                out[0]  = v / (float)B_CONST;
                g_count = 0;            // reset for next graph replay
            }
        }
    }
}

extern "C" void kernel_launch(void* const* d_in, const int* in_sizes, int n_in,
                              void* d_out, int out_size)
{
    const float* post = (const float*)d_in[0];   // (B, S, 2) f32 interleaved
    const int*   len  = (const int*)d_in[1];     // (B,) int32 on device
    float*       out  = (float*)d_out;           // scalar f32

    ekl_fused_kernel<<<GRID, THREADS>>>(post, len, out);
}

// round 4
// speedup vs baseline: 1.2194x; 1.2194x over previous
#include <cuda_runtime.h>
#include <cuda_bf16.h>

// Problem constants: B=512, S=32768, alpha=0.1, beta=0.9
#define B_CONST 512
#define S_CONST 32768

// log(0.1), log(0.9). Note log(1-alpha)=log(beta), log(1-beta)=log(alpha).
#define LOG_A   (-2.3025850929940457f)   // log(0.1)
#define LOG_1A  (-0.10536051565782628f)  // log(0.9)
#define LOG_B   (-0.10536051565782628f)  // log(0.9)
#define LOG_1B  (-2.3025850929940457f)   // log(0.1)

constexpr int THREADS = 256;
constexpr int IT      = 8;                  // s-values per thread (no spills)
constexpr int CHUNK   = THREADS * IT;       // 2048 s per block
constexpr int BPR     = S_CONST / CHUNK;    // 16 blocks per row
constexpr int GRID    = B_CONST * BPR;      // 8192 blocks

__device__ float        g_partials[GRID];
__device__ unsigned int g_count;            // zero-init; last block resets

// KL transition term: prev=(pp0,pp1), curr=(q0,q1)
__device__ __forceinline__ float div_term(float pp0, float pp1,
                                          float q0, float q1)
{
    float l0 = __logf(q0);
    float l1 = __logf(q1);
    float t1 = q1 * (l1 - LOG_B)  + q0 * (l0 - LOG_1B);
    float t2 = q1 * (l1 - LOG_1B) + q0 * (l0 - LOG_B);
    return pp1 * t1 + pp0 * t2;
}

__global__ __launch_bounds__(THREADS)
void ekl_fused_kernel(const float* __restrict__ post,
                      const int* __restrict__ length,
                      float* __restrict__ out)
{
    const int bid = blockIdx.x;
    const int b   = bid / BPR;
    const int c   = bid % BPR;
    const int len = length[b];        // 1 <= len <= S (int32)
    const int s0  = c * CHUNK;

    float sum = 0.0f;

    if (s0 < len) {
        const float2* row = reinterpret_cast<const float2*>(post)
                            + (size_t)b * S_CONST;
        const int sbase = s0 + threadIdx.x * IT;

        if (sbase < len) {
            // 4 consecutive float4 loads (64B/thread, 16B-aligned),
            // streaming (evict-first): data is touched exactly once.
            float c0[IT], c1[IT];
            const float4* v = reinterpret_cast<const float4*>(row + sbase);
            #pragma unroll
            for (int i = 0; i < IT / 2; ++i) {
                float4 q = __ldcs(v + i);
                c0[2*i]   = q.x; c1[2*i]   = q.y;
                c0[2*i+1] = q.z; c1[2*i+1] = q.w;
            }

            if (sbase > 0 && sbase + IT <= len) {
                // Fast path: all IT transitions valid, no per-element checks.
                float2 pv = __ldcs(row + (sbase - 1));
                float pp0 = pv.x, pp1 = pv.y;
                #pragma unroll
                for (int i = 0; i < IT; ++i) {
                    sum += div_term(pp0, pp1, c0[i], c1[i]);
                    pp0 = c0[i]; pp1 = c1[i];
                }
            } else {
                // Slow path: chunk head (s==0 first term) or masked tail.
                float pp0, pp1;
                if (sbase > 0) {
                    float2 pv = __ldcs(row + (sbase - 1));
                    pp0 = pv.x; pp1 = pv.y;
                } else {
                    float l0 = __logf(c0[0]);
                    float l1 = __logf(c1[0]);
                    sum += c1[0] * (l1 - LOG_A) + c0[0] * (l0 - LOG_1A);
                    pp0 = 0.0f; pp1 = 0.0f;   // unused (s>=1 guard)
                }
                #pragma unroll
                for (int i = 0; i < IT; ++i) {
                    const int s = sbase + i;
                    if (s >= 1 && s < len)
                        sum += div_term(pp0, pp1, c0[i], c1[i]);
                    pp0 = c0[i]; pp1 = c1[i];
                }
            }
        }
    }

    // Deterministic block reduction: warp shuffle tree + smem
    #pragma unroll
    for (int off = 16; off > 0; off >>= 1)
        sum += __shfl_down_sync(0xffffffffu, sum, off);

    __shared__ float wsum[THREADS / 32];
    const int lane = threadIdx.x & 31;
    const int wid  = threadIdx.x >> 5;
    if (lane == 0) wsum[wid] = sum;
    __syncthreads();

    if (wid == 0) {
        float v = (lane < THREADS / 32) ? wsum[lane] : 0.0f;
        #pragma unroll
        for (int off = 4; off > 0; off >>= 1)
            v += __shfl_down_sync(0xffffffffu, v, off);
        if (lane == 0) g_partials[bid] = v;
    }

    // Last-block-wins final reduction (single launch, graph-replayable).
    __shared__ bool is_last;
    if (threadIdx.x == 0) {
        __threadfence();
        unsigned int t = atomicAdd(&g_count, 1u);
        is_last = (t == GRID - 1);
    }
    __syncthreads();

    if (is_last) {
        __threadfence();
        // Fixed per-thread strided order -> deterministic.
        float s = 0.0f;
        #pragma unroll
        for (int i = 0; i < GRID / THREADS; ++i)
            s += g_partials[threadIdx.x + i * THREADS];

        #pragma unroll
        for (int off = 16; off > 0; off >>= 1)
            s += __shfl_down_sync(0xffffffffu, s, off);

        if (lane == 0) wsum[wid] = s;
        __syncthreads();

        if (wid == 0) {
            float v = (lane < THREADS / 32) ? wsum[lane] : 0.0f;
            #pragma unroll
            for (int off = 4; off > 0; off >>= 1)
                v += __shfl_down_sync(0xffffffffu, v, off);
            if (lane == 0) {
                out[0]  = v / (float)B_CONST;
                g_count = 0;            // reset for next graph replay
            }
        }
    }
}

extern "C" void kernel_launch(void* const* d_in, const int* in_sizes, int n_in,
                              void* d_out, int out_size)
{
    const float* post = (const float*)d_in[0];   // (B, S, 2) f32 interleaved
    const int*   len  = (const int*)d_in[1];     // (B,) int32 on device
    float*       out  = (float*)d_out;           // scalar f32

    ekl_fused_kernel<<<GRID, THREADS>>>(post, len, out);
}

// round 5
// speedup vs baseline: 1.4168x; 1.1618x over previous
#include <cuda_runtime.h>
#include <cuda_bf16.h>

// Problem constants: B=512, S=32768, alpha=0.1, beta=0.9
#define B_CONST 512
#define S_CONST 32768

// log(0.1), log(0.9). Note log(1-alpha)=log(beta), log(1-beta)=log(alpha).
#define LOG_A   (-2.3025850929940457f)   // log(0.1)
#define LOG_1A  (-0.10536051565782628f)  // log(0.9)
#define LOG_B   (-0.10536051565782628f)  // log(0.9)
#define LOG_1B  (-2.3025850929940457f)   // log(0.1)

constexpr int THREADS = 256;
constexpr int IT      = 8;                  // s-values per thread
constexpr int CHUNK   = THREADS * IT;       // 2048 s per block
constexpr int BPR     = S_CONST / CHUNK;    // 16 blocks per row
constexpr int GRID    = B_CONST * BPR;      // 8192 blocks

__device__ float g_partials[GRID];

__global__ __launch_bounds__(THREADS)
void ekl_main_kernel(const float* __restrict__ post,
                     const int* __restrict__ length)
{
    const int bid = blockIdx.x;
    const int b   = bid / BPR;
    const int c   = bid % BPR;
    const int len = length[b];        // 1 <= len <= S (int32)
    const int s0  = c * CHUNK;

    float sum = 0.0f;

    if (s0 < len) {
        const float2* row = reinterpret_cast<const float2*>(post)
                            + (size_t)b * S_CONST;
        const int sbase = s0 + threadIdx.x * IT;

        if (sbase < len) {
            // 4 consecutive float4 loads (64B/thread, 16B-aligned).
            float c0[IT], c1[IT];
            const float4* v = reinterpret_cast<const float4*>(row + sbase);
            #pragma unroll
            for (int i = 0; i < IT / 2; ++i) {
                float4 q = v[i];
                c0[2*i]   = q.x; c1[2*i]   = q.y;
                c0[2*i+1] = q.z; c1[2*i+1] = q.w;
            }

            float pp0, pp1;
            if (sbase > 0) {
                float2 pv = row[sbase - 1];
                pp0 = pv.x; pp1 = pv.y;
            } else {
                // first-term contribution at s = 0 (len >= 1 always)
                float l0 = __logf(c0[0]);
                float l1 = __logf(c1[0]);
                sum += c1[0] * (l1 - LOG_A) + c0[0] * (l0 - LOG_1A);
                pp0 = 0.0f; pp1 = 0.0f;   // unused (s>=1 guard below)
            }

            #pragma unroll
            for (int i = 0; i < IT; ++i) {
                const int s = sbase + i;
                if (s >= 1 && s < len) {
                    float q0 = c0[i], q1 = c1[i];
                    float l0 = __logf(q0);
                    float l1 = __logf(q1);
                    float t1 = q1 * (l1 - LOG_B)  + q0 * (l0 - LOG_1B);
                    float t2 = q1 * (l1 - LOG_1B) + q0 * (l0 - LOG_B);
                    sum += pp1 * t1 + pp0 * t2;
                }
                pp0 = c0[i]; pp1 = c1[i];
            }
        }
    }

    // Deterministic block reduction: warp shuffle tree + smem
    #pragma unroll
    for (int off = 16; off > 0; off >>= 1)
        sum += __shfl_down_sync(0xffffffffu, sum, off);

    __shared__ float wsum[THREADS / 32];
    const int lane = threadIdx.x & 31;
    const int wid  = threadIdx.x >> 5;
    if (lane == 0) wsum[wid] = sum;
    __syncthreads();

    if (wid == 0) {
        float v = (lane < THREADS / 32) ? wsum[lane] : 0.0f;
        #pragma unroll
        for (int off = 4; off > 0; off >>= 1)
            v += __shfl_down_sync(0xffffffffu, v, off);
        if (lane == 0) g_partials[bid] = v;
    }
}

// Final reduction: 1024 threads, each loads 2 float4 (coalesced, MLP=2).
__global__ __launch_bounds__(1024)
void ekl_final_kernel(float* __restrict__ out)
{
    const float4* p4 = reinterpret_cast<const float4*>(g_partials);
    // 8192 floats = 2048 float4; 1024 threads * 2 each. Fixed order.
    float4 a = p4[threadIdx.x];
    float4 b = p4[threadIdx.x + 1024];
    float s = (a.x + a.y) + (a.z + a.w) + (b.x + b.y) + (b.z + b.w);

    #pragma unroll
    for (int off = 16; off > 0; off >>= 1)
        s += __shfl_down_sync(0xffffffffu, s, off);

    __shared__ float wsum[32];
    const int lane = threadIdx.x & 31;
    const int wid  = threadIdx.x >> 5;
    if (lane == 0) wsum[wid] = s;
    __syncthreads();

    if (wid == 0) {
        float v = wsum[lane];   // exactly 32 warps
        #pragma unroll
        for (int off = 16; off > 0; off >>= 1)
            v += __shfl_down_sync(0xffffffffu, v, off);
        if (lane == 0) out[0] = v / (float)B_CONST;
    }
}

extern "C" void kernel_launch(void* const* d_in, const int* in_sizes, int n_in,
                              void* d_out, int out_size)
{
    const float* post = (const float*)d_in[0];   // (B, S, 2) f32 interleaved
    const int*   len  = (const int*)d_in[1];     // (B,) int32 on device
    float*       out  = (float*)d_out;           // scalar f32

    ekl_main_kernel<<<GRID, THREADS>>>(post, len);
    ekl_final_kernel<<<1, 1024>>>(out);
}